// round 16
// baseline (speedup 1.0000x reference)
#include <cuda_runtime.h>
#include <math.h>

#define HID     256
#define SLOTS   64
#define NB      4
#define TSTEPS  256
#define BATCH   512
#define KSM     128          // k in [0,128) in SMEM; k in [128,256) in REGISTERS
#define NTH     256
#define EPSV    1e-5f

// Slot-memory scratch: 512 x 64 x 256 fp32 = 32 MB (L2-resident)
__device__ float g_mem[(size_t)BATCH * SLOTS * HID];

__device__ __forceinline__ float fast_tanh(float x) {
    float e = __expf(2.0f * x);
    return 1.0f - __fdividef(2.0f, e + 1.0f);
}

#define FFMA2(acc, a, b) \
    asm("fma.rn.f32x2 %0, %1, %2, %0;" : "+l"(acc) : "l"(a), "l"(b))

// phase-2 for one batch-pair: 8 rows x 2 batches over this thread's k-slice,
// 4 register-W groups (k>=128, instant-on) + 4 smem-W groups (k<128),
// then routed butterfly so lane ends with row rb+s. Outputs HN[2] (pre-LN).
#define RUN_PHASE2(VP, HN)                                                    \
    do {                                                                      \
        unsigned long long acc[8][2];                                         \
        _Pragma("unroll")                                                     \
        for (int r = 0; r < 8; r++) { acc[r][0] = 0ull; acc[r][1] = 0ull; }   \
        _Pragma("unroll")                                                     \
        for (int g = 0; g < 4; g++) {                                         \
            const float* vp0 = (VP) + (KSM + g * 32) + sK;                    \
            ulonglong2 va = *(const ulonglong2*)(vp0);                        \
            ulonglong2 vb = *(const ulonglong2*)(vp0 + HID);                  \
            _Pragma("unroll")                                                 \
            for (int r = 0; r < 8; r++) {                                     \
                ulonglong2 w2 = wr[g][r];                                     \
                FFMA2(acc[r][0], w2.x, va.x); FFMA2(acc[r][0], w2.y, va.y);   \
                FFMA2(acc[r][1], w2.x, vb.x); FFMA2(acc[r][1], w2.y, vb.y);   \
            }                                                                 \
        }                                                                     \
        _Pragma("unroll")                                                     \
        for (int jj = 0; jj < 4; jj++) {                                      \
            const float* vp0 = (VP) + jj * 32 + sK;                           \
            ulonglong2 va = *(const ulonglong2*)(vp0);                        \
            ulonglong2 vb = *(const ulonglong2*)(vp0 + HID);                  \
            _Pragma("unroll")                                                 \
            for (int r = 0; r < 8; r++) {                                     \
                ulonglong2 w2 = *(const ulonglong2*)(wsm + r * KSM + jj * 32);\
                FFMA2(acc[r][0], w2.x, va.x); FFMA2(acc[r][0], w2.y, va.y);   \
                FFMA2(acc[r][1], w2.x, vb.x); FFMA2(acc[r][1], w2.y, vb.y);   \
            }                                                                 \
        }                                                                     \
        float P[8][2];                                                        \
        _Pragma("unroll")                                                     \
        for (int r = 0; r < 8; r++)                                           \
            _Pragma("unroll")                                                 \
            for (int bb = 0; bb < 2; bb++) {                                  \
                float lo = __uint_as_float((unsigned)(acc[r][bb] & 0xffffffffu)); \
                float hi = __uint_as_float((unsigned)(acc[r][bb] >> 32));     \
                P[r][bb] = lo + hi;                                           \
            }                                                                 \
        float Q[4][2];                                                        \
        _Pragma("unroll")                                                     \
        for (int r = 0; r < 4; r++)                                           \
            _Pragma("unroll")                                                 \
            for (int bb = 0; bb < 2; bb++) {                                  \
                float keep = h4 ? P[r + 4][bb] : P[r][bb];                    \
                float send = h4 ? P[r][bb]     : P[r + 4][bb];                \
                Q[r][bb] = keep + __shfl_xor_sync(0xffffffffu, send, 4);      \
            }                                                                 \
        float R2[2][2];                                                       \
        _Pragma("unroll")                                                     \
        for (int r = 0; r < 2; r++)                                           \
            _Pragma("unroll")                                                 \
            for (int bb = 0; bb < 2; bb++) {                                  \
                float keep = h2 ? Q[r + 2][bb] : Q[r][bb];                    \
                float send = h2 ? Q[r][bb]     : Q[r + 2][bb];                \
                R2[r][bb] = keep + __shfl_xor_sync(0xffffffffu, send, 2);     \
            }                                                                 \
        _Pragma("unroll")                                                     \
        for (int bb = 0; bb < 2; bb++) {                                      \
            float keep = h1 ? R2[1][bb] : R2[0][bb];                          \
            float send = h1 ? R2[0][bb] : R2[1][bb];                          \
            float u = keep + __shfl_xor_sync(0xffffffffu, send, 1);           \
            (HN)[bb] = fast_tanh(u + bu_i);                                   \
        }                                                                     \
    } while (0)

// next-step v precompute: A[bb] for batch pair BB (uses pre-shift m, pf)
#define PREP_A(BB, A2)                                                        \
    do {                                                                      \
        _Pragma("unroll")                                                     \
        for (int bb = 0; bb < 2; bb++) {                                      \
            int b = (BB) + bb;                                                \
            float pre = wnp[4] * pf[b];                                       \
            _Pragma("unroll")                                                 \
            for (int k = 0; k < 4; k++) pre = fmaf(wnp[k], m[b][k + 1], pre); \
            float embp = fast_tanh(fmaf(xsm[b * TSTEPS + tn], We_i, be_i));   \
            (A2)[bb] = fmaf(cs, pre, embp);                                   \
        }                                                                     \
    } while (0)

// routed LN warp reduction for 2 batches (4 quantities), 6 shfl total;
// lane<4 publishes q = lane: {sum_b0, sum_b1, sq_b0, sq_b1}
#define LN_PUBLISH(HN, REDP)                                                  \
    do {                                                                      \
        float r4[4] = { (HN)[0], (HN)[1], (HN)[0]*(HN)[0], (HN)[1]*(HN)[1] }; \
        float a2[2];                                                          \
        {                                                                     \
            float keep = l1b ? r4[1] : r4[0];                                 \
            float send = l1b ? r4[0] : r4[1];                                 \
            a2[0] = keep + __shfl_xor_sync(0xffffffffu, send, 1);             \
            keep = l1b ? r4[3] : r4[2];                                       \
            send = l1b ? r4[2] : r4[3];                                       \
            a2[1] = keep + __shfl_xor_sync(0xffffffffu, send, 1);             \
        }                                                                     \
        float c1;                                                             \
        {                                                                     \
            float keep = l2b ? a2[1] : a2[0];                                 \
            float send = l2b ? a2[0] : a2[1];                                 \
            c1 = keep + __shfl_xor_sync(0xffffffffu, send, 2);                \
        }                                                                     \
        c1 += __shfl_xor_sync(0xffffffffu, c1, 4);                            \
        c1 += __shfl_xor_sync(0xffffffffu, c1, 8);                            \
        c1 += __shfl_xor_sync(0xffffffffu, c1, 16);                           \
        if (lane < 4) (REDP)[warp * 4 + lane] = c1;                           \
    } while (0)

// pipeline tail: cross-warp LN sums -> hb -> v(t+1) STS -> slot flush/shift
#define TAIL(REDP, HN, A2, BB, VDST)                                          \
    do {                                                                      \
        float4 S = make_float4(0.f, 0.f, 0.f, 0.f);                          \
        _Pragma("unroll")                                                     \
        for (int w = 0; w < 8; w++) {                                         \
            float4 a4 = *(const float4*)((REDP) + w * 4);                     \
            S.x += a4.x; S.y += a4.y; S.z += a4.z; S.w += a4.w;               \
        }                                                                     \
        float sums[2] = { S.x, S.y }, sqs[2] = { S.z, S.w };                  \
        _Pragma("unroll")                                                     \
        for (int bb = 0; bb < 2; bb++) {                                      \
            int b = (BB) + bb;                                                \
            float mu  = sums[bb] * (1.0f / HID);                              \
            float var = fmaf(sqs[bb], 1.0f / HID, -mu * mu);                  \
            float hbv = ((HN)[bb] - mu) * rsqrtf(var + EPSV) * g_i + bt_i;    \
            h[b] = hbv;                                                       \
            (VDST)[bb * HID + i] = fmaf(Bc, hbv, (A2)[bb]);                   \
            col[b][s_out] = fmaf(wn[0], hbv, m[b][0]);                        \
            m[b][0] = fmaf(wn[1], hbv, m[b][1]);                              \
            m[b][1] = fmaf(wn[2], hbv, m[b][2]);                              \
            m[b][2] = fmaf(wn[3], hbv, m[b][3]);                              \
            m[b][3] = fmaf(wn[4], hbv, m[b][4]);                              \
            m[b][4] = pf[b];                                                  \
        }                                                                     \
    } while (0)

__global__ void __launch_bounds__(NTH, 1)
postnorm_rnn_kernel(const float* __restrict__ x,        // [512,256,1]
                    const float* __restrict__ W_embed,  // [256]
                    const float* __restrict__ b_embed,  // [256]
                    const float* __restrict__ W_update, // [256,256]
                    const float* __restrict__ b_update, // [256]
                    const float* __restrict__ gamma,    // [256]
                    const float* __restrict__ beta,     // [256]
                    const float* __restrict__ W_out,    // [10,256]
                    const float* __restrict__ b_out,    // [10]
                    const float* __restrict__ cs_in,    // [1]
                    float* __restrict__ out)            // [512,10]
{
    extern __shared__ float smem[];
    float* sW   = smem;                          // 256 rows x 128 cols = 32768 f
    float* vrX  = sW + HID * KSM;                // [2][256] pipeline X  =  512 f
    float* vrY  = vrX + 2 * HID;                 // [2][256] pipeline Y  =  512 f
    float* xsm  = vrY + 2 * HID;                 // [b][t] 4*256        = 1024 f
    float* wtab = xsm + NB * TSTEPS;             // 64*5                =  320 f
    float* stab = wtab + 320;                    // 64 transition S
    float* redX = stab + 64;                     // 8 warps x 4         =   32 f
    float* redY = redX + 32;                     //                       32 f
    float* osm  = redY + 32;                     // 160*4               =  640 f

    const int tid  = threadIdx.x;
    const int i    = tid;                 // hidden index owned
    const int b0   = blockIdx.x * NB;
    const int warp = tid >> 5;
    const int lane = tid & 31;
    const int s    = tid & 7;             // k-slice id
    const int rb   = tid & ~7;            // rows rb..rb+7
    const int sK   = s * 4;
    const bool h4 = (s & 4), h2 = (s & 2), h1 = (s & 1);
    const bool l1b = lane & 1, l2b = lane & 2;

    // ---- zero this CTA's slot-memory slice ----
    {
        float4* mz = (float4*)(g_mem + (size_t)b0 * SLOTS * HID);
        for (int k = tid; k < NB * SLOTS * HID / 4; k += NTH)
            mz[k] = make_float4(0.f, 0.f, 0.f, 0.f);
    }
    // ---- stage W_update[:, 0:128] into SMEM (row-major, stride 128) ----
    {
        for (int idx = tid; idx < HID * (KSM / 4); idx += NTH) {
            int r = idx >> 5;              // 32 float4 per row
            int c = idx & 31;
            ((float4*)(sW + r * KSM))[c] =
                ((const float4*)(W_update + (size_t)r * HID))[c];
        }
    }
    // ---- stage x: xsm[b][t] ----
    {
        int b = tid >> 6, t4 = tid & 63;
        ((float4*)xsm)[tid] =
            ((const float4*)(x + (size_t)(b0 + b) * TSTEPS))[t4];
    }
    // ---- precompute softmax weights + transition scalars S[base] ----
    if (tid < SLOTS) {
        int base = tid;
        float e[5], sum = 0.f, ep[5], sump = 0.f;
        int basep = (base + 1) & (SLOTS - 1);
#pragma unroll
        for (int k = 0; k < 5; k++) {
            int ix  = (base  + k - 2 + SLOTS) & (SLOTS - 1);
            int ixp = (basep + k - 2 + SLOTS) & (SLOTS - 1);
            float d  = (float)(ix  - base);
            float dp = (float)(ixp - basep);
            e[k]  = expf(-0.125f * d * d);   sum  += e[k];
            ep[k] = expf(-0.125f * dp * dp); sump += ep[k];
        }
        float inv = 1.0f / sum, invp = 1.0f / sump;
        float S = 0.f;
#pragma unroll
        for (int k = 0; k < 5; k++) {
            wtab[base * 5 + k] = e[k] * inv;
            if (k < 4) S += (ep[k] * invp) * (e[k + 1] * inv);
        }
        stab[base] = S;
    }

    const float cs   = 1.0f / (1.0f + expf(-cs_in[0]));
    const float We_i = W_embed[i];
    const float be_i = b_embed[i];
    const float bu_i = b_update[i];
    const float g_i  = gamma[i];
    const float bt_i = beta[i];

    float h[NB];
    float m[NB][5];
    float* col[NB];
#pragma unroll
    for (int b = 0; b < NB; b++) {
        h[b] = 0.f;
        col[b] = g_mem + (size_t)(b0 + b) * SLOTS * HID + i;
#pragma unroll
        for (int k = 0; k < 5; k++) m[b][k] = 0.f;
    }

    // ---- hoist W k-tail (k in [128,256)) into REGISTERS, once ----
    ulonglong2 wr[4][8];
#pragma unroll
    for (int g = 0; g < 4; g++)
#pragma unroll
        for (int r = 0; r < 8; r++)
            wr[g][r] = __ldg((const ulonglong2*)
                (W_update + (size_t)(rb + r) * HID + (KSM + g * 32) + sK));

    const float* wsm = sW + rb * KSM + sK;

    __syncthreads();   // init visible

    // ---- t=0 inputs: ctx = 0, h = 0 -> v = tanh(x0*We+be) ----
#pragma unroll
    for (int bb = 0; bb < 2; bb++) {
        vrX[bb * HID + i] = fast_tanh(fmaf(xsm[bb * TSTEPS], We_i, be_i));
        vrY[bb * HID + i] = fast_tanh(fmaf(xsm[(bb + 2) * TSTEPS], We_i, be_i));
    }
    __syncthreads();

    for (int t = 0; t < TSTEPS; t++) {
        const int base  = t & (SLOTS - 1);
        const int s_in  = ((base + 3)  & (SLOTS - 1)) * HID;
        const int s_out = ((base + 62) & (SLOTS - 1)) * HID;
        const int tn    = (t + 1) & (TSTEPS - 1);
        const int basep = (t + 1) & (SLOTS - 1);

        float pf[NB];
#pragma unroll
        for (int b = 0; b < NB; b++) pf[b] = col[b][s_in];

        float wn[5], wnp[5];
#pragma unroll
        for (int k = 0; k < 5; k++) { wn[k] = wtab[base * 5 + k];
                                      wnp[k] = wtab[basep * 5 + k]; }
        const float Bc = fmaf(cs, stab[base], 1.0f);

        // ======== pipeline X: batches 0,1 ========
        float hnX[2];
        RUN_PHASE2(vrX, hnX);
        float AX[2];
        PREP_A(0, AX);                 // independent; fills shfl latency
        LN_PUBLISH(hnX, redX);
        __syncthreads();               // bar1: redX visible; vrY(t) visible

        // X-tail (depends on redX) runs interleaved with phase-2 Y (independent)
        TAIL(redX, hnX, AX, 0, vrX);   // writes vrX(t+1)

        // ======== pipeline Y: batches 2,3 ========
        float hnY[2];
        RUN_PHASE2(vrY, hnY);
        float AY[2];
        PREP_A(2, AY);
        LN_PUBLISH(hnY, redY);
        __syncthreads();               // bar2: redY visible; vrX(t+1) visible

        TAIL(redY, hnY, AY, 2, vrY);   // writes vrY(t+1); visible at next bar1
    }

    // ---- output: out[b,:] = h[b] @ W_out^T + b_out (reuse xsm as h buffer) ----
    __syncthreads();
#pragma unroll
    for (int b = 0; b < NB; b++) xsm[b * HID + i] = h[b];
    __syncthreads();
    if (tid < 160) {                       // 16 segments x 10 outputs
        int o = tid % 10, seg = tid / 10;
        float a0 = 0.f, a1 = 0.f, a2 = 0.f, a3 = 0.f;
#pragma unroll
        for (int jj = 0; jj < 16; jj++) {
            int ii = seg * 16 + jj;
            float w = W_out[o * HID + ii];
            a0 = fmaf(w, xsm[0 * HID + ii], a0);
            a1 = fmaf(w, xsm[1 * HID + ii], a1);
            a2 = fmaf(w, xsm[2 * HID + ii], a2);
            a3 = fmaf(w, xsm[3 * HID + ii], a3);
        }
        osm[tid * 4 + 0] = a0; osm[tid * 4 + 1] = a1;
        osm[tid * 4 + 2] = a2; osm[tid * 4 + 3] = a3;
    }
    __syncthreads();
    if (tid < NB * 10) {
        int o = tid % 10, b = tid / 10;
        float sum = b_out[o];
#pragma unroll
        for (int seg = 0; seg < 16; seg++)
            sum += osm[(seg * 10 + o) * 4 + b];
        out[(size_t)(b0 + b) * 10 + o] = sum;
    }
}

extern "C" void kernel_launch(void* const* d_in, const int* in_sizes, int n_in,
                              void* d_out, int out_size) {
    (void)in_sizes; (void)n_in; (void)out_size;
    const float* x        = (const float*)d_in[0];
    const float* W_embed  = (const float*)d_in[1];
    const float* b_embed  = (const float*)d_in[2];
    const float* W_update = (const float*)d_in[3];
    const float* b_update = (const float*)d_in[4];
    const float* gamma    = (const float*)d_in[5];
    const float* beta     = (const float*)d_in[6];
    const float* W_out    = (const float*)d_in[7];
    const float* b_out    = (const float*)d_in[8];
    const float* cs       = (const float*)d_in[9];

    const size_t SMEM_BYTES =
        (size_t)(HID * KSM + 4 * HID + NB * TSTEPS + 320 + 64 + 32 + 32 + 640)
        * sizeof(float);   // 143,616 B

    cudaFuncSetAttribute(postnorm_rnn_kernel,
                         cudaFuncAttributeMaxDynamicSharedMemorySize,
                         (int)SMEM_BYTES);

    postnorm_rnn_kernel<<<BATCH / NB, NTH, SMEM_BYTES>>>(
        x, W_embed, b_embed, W_update, b_update, gamma, beta,
        W_out, b_out, cs, (float*)d_out);
}

// round 17
// speedup vs baseline: 1.2840x; 1.2840x over previous
#include <cuda_runtime.h>
#include <math.h>

#define HID     256
#define SLOTS   64
#define NB      4
#define TSTEPS  256
#define BATCH   512
#define KSM     160          // k-columns of W in SMEM; k in [160,256) in REGISTERS
#define NTH     256
#define EPSV    1e-5f

// Slot-memory scratch: 512 x 64 x 256 fp32 = 32 MB (L2-resident)
__device__ float g_mem[(size_t)BATCH * SLOTS * HID];

__device__ __forceinline__ float fast_tanh(float x) {
    float e = __expf(2.0f * x);
    return 1.0f - __fdividef(2.0f, e + 1.0f);
}

#define FFMA2(acc, a, b) \
    asm("fma.rn.f32x2 %0, %1, %2, %0;" : "+l"(acc) : "l"(a), "l"(b))

// one k-group against SMEM-resident W
#define GRP_SMEM(JJ)                                                          \
    do {                                                                      \
        const int off = (JJ) * 32;                                            \
        ulonglong2 v0 = *(const ulonglong2*)(vbase + 0 * HID + off);          \
        ulonglong2 v1 = *(const ulonglong2*)(vbase + 1 * HID + off);          \
        ulonglong2 v2 = *(const ulonglong2*)(vbase + 2 * HID + off);          \
        ulonglong2 v3 = *(const ulonglong2*)(vbase + 3 * HID + off);          \
        _Pragma("unroll")                                                     \
        for (int r = 0; r < 8; r++) {                                         \
            ulonglong2 w2 = *(const ulonglong2*)(wsm + r * KSM + off);        \
            FFMA2(acc[r][0], w2.x, v0.x); FFMA2(acc[r][0], w2.y, v0.y);       \
            FFMA2(acc[r][1], w2.x, v1.x); FFMA2(acc[r][1], w2.y, v1.y);       \
            FFMA2(acc[r][2], w2.x, v2.x); FFMA2(acc[r][2], w2.y, v2.y);       \
            FFMA2(acc[r][3], w2.x, v3.x); FFMA2(acc[r][3], w2.y, v3.y);       \
        }                                                                     \
    } while (0)

// one k-group against REGISTER-resident W (k >= KSM)
#define GRP_REG(G)                                                            \
    do {                                                                      \
        const int off = KSM + (G) * 32;                                       \
        ulonglong2 v0 = *(const ulonglong2*)(vbase + 0 * HID + off);          \
        ulonglong2 v1 = *(const ulonglong2*)(vbase + 1 * HID + off);          \
        ulonglong2 v2 = *(const ulonglong2*)(vbase + 2 * HID + off);          \
        ulonglong2 v3 = *(const ulonglong2*)(vbase + 3 * HID + off);          \
        _Pragma("unroll")                                                     \
        for (int r = 0; r < 8; r++) {                                         \
            ulonglong2 w2 = wr[(G)][r];                                       \
            FFMA2(acc[r][0], w2.x, v0.x); FFMA2(acc[r][0], w2.y, v0.y);       \
            FFMA2(acc[r][1], w2.x, v1.x); FFMA2(acc[r][1], w2.y, v1.y);       \
            FFMA2(acc[r][2], w2.x, v2.x); FFMA2(acc[r][2], w2.y, v2.y);       \
            FFMA2(acc[r][3], w2.x, v3.x); FFMA2(acc[r][3], w2.y, v3.y);       \
        }                                                                     \
    } while (0)

__global__ void __launch_bounds__(NTH, 1)
postnorm_rnn_kernel(const float* __restrict__ x,        // [512,256,1]
                    const float* __restrict__ W_embed,  // [256]
                    const float* __restrict__ b_embed,  // [256]
                    const float* __restrict__ W_update, // [256,256]
                    const float* __restrict__ b_update, // [256]
                    const float* __restrict__ gamma,    // [256]
                    const float* __restrict__ beta,     // [256]
                    const float* __restrict__ W_out,    // [10,256]
                    const float* __restrict__ b_out,    // [10]
                    const float* __restrict__ cs_in,    // [1]
                    float* __restrict__ out)            // [512,10]
{
    extern __shared__ float smem[];
    float* sW    = smem;                         // 256 rows x 160 cols = 40960 f
    float* vrow  = sW + HID * KSM;               // [b][j] 4*256  =  1024 f
    float* xsm4  = vrow + NB * HID;              // [t][b] 256*4  =  1024 f
    float* wtab8 = xsm4 + TSTEPS * NB;           // [base][8]: wn0..4, S, pad
    float* red   = wtab8 + SLOTS * 8;            // 8 warps x 8   =    64 f
    float* osm   = red + 64;                     // 160*4         =   640 f

    const int tid  = threadIdx.x;
    const int i    = tid;                 // hidden index owned (phase1/LN/mem)
    const int b0   = blockIdx.x * NB;
    const int warp = tid >> 5;
    const int lane = tid & 31;
    const int s    = tid & 7;             // k-slice id (8 slices of 32 k)
    const int rb   = tid & ~7;            // row block: rows rb..rb+7
    const int sK   = s * 4;               // k offset within each 32-float group

    // ---- zero this CTA's slot-memory slice ----
    {
        float4* mz = (float4*)(g_mem + (size_t)b0 * SLOTS * HID);
        for (int k = tid; k < NB * SLOTS * HID / 4; k += NTH)
            mz[k] = make_float4(0.f, 0.f, 0.f, 0.f);
    }
    // ---- stage W_update[:, 0:160] into SMEM (row-major, stride 160) ----
    {
        for (int idx = tid; idx < HID * (KSM / 4); idx += NTH) {
            int r = idx / (KSM / 4);           // 40 float4 per row
            int c = idx % (KSM / 4);
            ((float4*)(sW + r * KSM))[c] =
                ((const float4*)(W_update + (size_t)r * HID))[c];
        }
    }
    // ---- stage x TRANSPOSED: xsm4[t*4 + b] = x[b][t] ----
    {
        for (int idx = tid; idx < TSTEPS * NB; idx += NTH) {
            int t = idx >> 2, b = idx & 3;
            xsm4[idx] = x[(size_t)(b0 + b) * TSTEPS + t];
        }
    }
    // ---- precompute packed weight table: wtab8[base] = {wn0..wn4, S, 0, 0} ----
    if (tid < SLOTS) {
        int base = tid;
        float e[5], sum = 0.f, ep[5], sump = 0.f;
        int basep = (base + 1) & (SLOTS - 1);
#pragma unroll
        for (int k = 0; k < 5; k++) {
            int ix  = (base  + k - 2 + SLOTS) & (SLOTS - 1);
            int ixp = (basep + k - 2 + SLOTS) & (SLOTS - 1);
            float d  = (float)(ix  - base);
            float dp = (float)(ixp - basep);
            e[k]  = expf(-0.125f * d * d);   sum  += e[k];
            ep[k] = expf(-0.125f * dp * dp); sump += ep[k];
        }
        float inv = 1.0f / sum, invp = 1.0f / sump;
        float S = 0.f;
#pragma unroll
        for (int k = 0; k < 5; k++) {
            wtab8[base * 8 + k] = e[k] * inv;
            if (k < 4) S += (ep[k] * invp) * (e[k + 1] * inv);
        }
        wtab8[base * 8 + 5] = S;   // window-shift coupling scalar
        wtab8[base * 8 + 6] = 0.f;
        wtab8[base * 8 + 7] = 0.f;
    }

    const float cs   = 1.0f / (1.0f + expf(-cs_in[0]));
    const float We_i = W_embed[i];
    const float be_i = b_embed[i];
    const float bu_i = b_update[i];
    const float g_i  = gamma[i];
    const float bt_i = beta[i];

    float h[NB];
    float m[NB][5];
    float* col[NB];
#pragma unroll
    for (int b = 0; b < NB; b++) {
        h[b] = 0.f;
        col[b] = g_mem + (size_t)(b0 + b) * SLOTS * HID + i;
#pragma unroll
        for (int k = 0; k < 5; k++) m[b][k] = 0.f;
    }

    // ---- hoist W k-tail (k in [160,256), 3 groups) into REGISTERS, once ----
    ulonglong2 wr[3][8];
#pragma unroll
    for (int g = 0; g < 3; g++)
#pragma unroll
        for (int r = 0; r < 8; r++)
            wr[g][r] = __ldg((const ulonglong2*)
                (W_update + (size_t)(rb + r) * HID + (KSM + g * 32) + sK));

    const float* wsm   = sW + rb * KSM + sK;     // smem W, k<160
    const float* vbase = vrow + sK;

    __syncthreads();   // init visible

    // ---- vrow(0): ctx = 0, h = 0 -> v = tanh(x0*We+be) ----
#pragma unroll
    for (int b = 0; b < NB; b++)
        vrow[b * HID + i] = fast_tanh(fmaf(xsm4[b], We_i, be_i));
    __syncthreads();

    for (int t = 0; t < TSTEPS; t++) {
        const int base  = t & (SLOTS - 1);
        const int s_in  = ((base + 3)  & (SLOTS - 1)) * HID;
        const int s_out = ((base + 62) & (SLOTS - 1)) * HID;

        float pf[NB];
#pragma unroll
        for (int b = 0; b < NB; b++) pf[b] = col[b][s_in];

        // packed table loads: wn[0..4] + S via two LDS.128
        float wn[5], Sc;
        {
            float4 a = *(const float4*)(wtab8 + base * 8);
            float4 c = *(const float4*)(wtab8 + base * 8 + 4);
            wn[0] = a.x; wn[1] = a.y; wn[2] = a.z; wn[3] = a.w;
            wn[4] = c.x; Sc = c.y;
        }

        // ---- phase 2: interleaved smem/register W groups ----
        unsigned long long acc[8][4];
#pragma unroll
        for (int r = 0; r < 8; r++)
#pragma unroll
            for (int b = 0; b < 4; b++) acc[r][b] = 0ull;

        GRP_REG(0);  GRP_SMEM(0);
        GRP_REG(1);  GRP_SMEM(1);
        GRP_REG(2);  GRP_SMEM(2);
        GRP_SMEM(3); GRP_SMEM(4);

        // ---- unpack partials ----
        float P[8][4];
#pragma unroll
        for (int r = 0; r < 8; r++)
#pragma unroll
            for (int b = 0; b < 4; b++) {
                float lo = __uint_as_float((unsigned)(acc[r][b] & 0xffffffffu));
                float hi = __uint_as_float((unsigned)(acc[r][b] >> 32));
                P[r][b] = lo + hi;
            }

        // ---- next-step prep (independent; fills shuffle latency below) ----
        const int  tn = (t + 1) & (TSTEPS - 1);
        const int  basep = (t + 1) & (SLOTS - 1);
        const float Bc = fmaf(cs, Sc, 1.0f);
        float wnp[5];
        {
            float4 a = *(const float4*)(wtab8 + basep * 8);
            wnp[0] = a.x; wnp[1] = a.y; wnp[2] = a.z; wnp[3] = a.w;
            wnp[4] = wtab8[basep * 8 + 4];
        }
        float A[NB];
        {
            float4 xq = *(const float4*)(xsm4 + tn * 4);
            float xv[4] = { xq.x, xq.y, xq.z, xq.w };
#pragma unroll
            for (int b = 0; b < NB; b++) {
                float pre = wnp[4] * pf[b];
#pragma unroll
                for (int k = 0; k < 4; k++) pre = fmaf(wnp[k], m[b][k + 1], pre);
                float embp = fast_tanh(fmaf(xv[b], We_i, be_i));
                A[b] = fmaf(cs, pre, embp);
            }
        }

        // ---- routed butterfly over 8 k-slices: lane ends with row rb+s ----
        const bool h4 = (s & 4), h2 = (s & 2), h1 = (s & 1);
        float Q[4][4];
#pragma unroll
        for (int r = 0; r < 4; r++)
#pragma unroll
            for (int b = 0; b < 4; b++) {
                float keep = h4 ? P[r + 4][b] : P[r][b];
                float send = h4 ? P[r][b]     : P[r + 4][b];
                Q[r][b] = keep + __shfl_xor_sync(0xffffffffu, send, 4);
            }
        float R2[2][4];
#pragma unroll
        for (int r = 0; r < 2; r++)
#pragma unroll
            for (int b = 0; b < 4; b++) {
                float keep = h2 ? Q[r + 2][b] : Q[r][b];
                float send = h2 ? Q[r][b]     : Q[r + 2][b];
                R2[r][b] = keep + __shfl_xor_sync(0xffffffffu, send, 2);
            }
        float hn[NB];
#pragma unroll
        for (int b = 0; b < 4; b++) {
            float keep = h1 ? R2[1][b] : R2[0][b];
            float send = h1 ? R2[0][b] : R2[1][b];
            float u = keep + __shfl_xor_sync(0xffffffffu, send, 1);
            hn[b] = fast_tanh(u + bu_i);
        }

        // ---- LayerNorm: routed multi-value warp reduction (11 shfl) ----
        float r8[8];
#pragma unroll
        for (int b = 0; b < NB; b++) { r8[b] = hn[b]; r8[4 + b] = hn[b] * hn[b]; }
        const bool l1 = lane & 1, l2 = lane & 2, l4 = lane & 4;
        float a4v[4];
#pragma unroll
        for (int j = 0; j < 4; j++) {
            float keep = l1 ? r8[2 * j + 1] : r8[2 * j];
            float send = l1 ? r8[2 * j]     : r8[2 * j + 1];
            a4v[j] = keep + __shfl_xor_sync(0xffffffffu, send, 1);
        }
        float b2v[2];
#pragma unroll
        for (int j = 0; j < 2; j++) {
            float keep = l2 ? a4v[2 * j + 1] : a4v[2 * j];
            float send = l2 ? a4v[2 * j]     : a4v[2 * j + 1];
            b2v[j] = keep + __shfl_xor_sync(0xffffffffu, send, 2);
        }
        float c1;
        {
            float keep = l4 ? b2v[1] : b2v[0];
            float send = l4 ? b2v[0] : b2v[1];
            c1 = keep + __shfl_xor_sync(0xffffffffu, send, 4);
        }
        c1 += __shfl_xor_sync(0xffffffffu, c1, 8);
        c1 += __shfl_xor_sync(0xffffffffu, c1, 16);
        if (lane < 8) red[warp * 8 + lane] = c1;   // q == lane
        __syncthreads();   // bar2: red visible; all vrow(t) reads complete

        float4 S1 = make_float4(0.f, 0.f, 0.f, 0.f);
        float4 S2 = make_float4(0.f, 0.f, 0.f, 0.f);
#pragma unroll
        for (int w = 0; w < 8; w++) {
            float4 a4 = *(const float4*)(red + w * 8);
            float4 c4 = *(const float4*)(red + w * 8 + 4);
            S1.x += a4.x; S1.y += a4.y; S1.z += a4.z; S1.w += a4.w;
            S2.x += c4.x; S2.y += c4.y; S2.z += c4.z; S2.w += c4.w;
        }
        float s1a[4] = {S1.x, S1.y, S1.z, S1.w};
        float s2a[4] = {S2.x, S2.y, S2.z, S2.w};

        // ---- critical tail: hb -> one FMA -> STS ----
        float hb[NB];
#pragma unroll
        for (int b = 0; b < NB; b++) {
            float mu  = s1a[b] * (1.0f / HID);
            float var = fmaf(s2a[b], 1.0f / HID, -mu * mu);
            hb[b] = (hn[b] - mu) * rsqrtf(var + EPSV) * g_i + bt_i;
            vrow[b * HID + i] = fmaf(Bc, hb[b], A[b]);   // v(t+1)
        }
        __syncthreads();   // bar1: vrow(t+1) visible for next phase-2

        // ---- off-path: slot flush + window shift ----
#pragma unroll
        for (int b = 0; b < NB; b++) {
            h[b] = hb[b];
            col[b][s_out] = fmaf(wn[0], hb[b], m[b][0]);
            m[b][0] = fmaf(wn[1], hb[b], m[b][1]);
            m[b][1] = fmaf(wn[2], hb[b], m[b][2]);
            m[b][2] = fmaf(wn[3], hb[b], m[b][3]);
            m[b][3] = fmaf(wn[4], hb[b], m[b][4]);
            m[b][4] = pf[b];
        }
    }

    // ---- output: out[b,:] = h[b] @ W_out^T + b_out ----
    __syncthreads();
#pragma unroll
    for (int b = 0; b < NB; b++) vrow[b * HID + i] = h[b];
    __syncthreads();
    if (tid < 160) {                       // 16 segments x 10 outputs
        int o = tid % 10, seg = tid / 10;
        float a0 = 0.f, a1 = 0.f, a2 = 0.f, a3 = 0.f;
#pragma unroll
        for (int jj = 0; jj < 16; jj++) {
            int ii = seg * 16 + jj;
            float w = W_out[o * HID + ii];
            a0 = fmaf(w, vrow[0 * HID + ii], a0);
            a1 = fmaf(w, vrow[1 * HID + ii], a1);
            a2 = fmaf(w, vrow[2 * HID + ii], a2);
            a3 = fmaf(w, vrow[3 * HID + ii], a3);
        }
        osm[tid * 4 + 0] = a0; osm[tid * 4 + 1] = a1;
        osm[tid * 4 + 2] = a2; osm[tid * 4 + 3] = a3;
    }
    __syncthreads();
    if (tid < NB * 10) {
        int o = tid % 10, b = tid / 10;
        float sum = b_out[o];
#pragma unroll
        for (int seg = 0; seg < 16; seg++)
            sum += osm[(seg * 10 + o) * 4 + b];
        out[(size_t)(b0 + b) * 10 + o] = sum;
    }
}

extern "C" void kernel_launch(void* const* d_in, const int* in_sizes, int n_in,
                              void* d_out, int out_size) {
    (void)in_sizes; (void)n_in; (void)out_size;
    const float* x        = (const float*)d_in[0];
    const float* W_embed  = (const float*)d_in[1];
    const float* b_embed  = (const float*)d_in[2];
    const float* W_update = (const float*)d_in[3];
    const float* b_update = (const float*)d_in[4];
    const float* gamma    = (const float*)d_in[5];
    const float* beta     = (const float*)d_in[6];
    const float* W_out    = (const float*)d_in[7];
    const float* b_out    = (const float*)d_in[8];
    const float* cs       = (const float*)d_in[9];

    const size_t SMEM_BYTES =
        (size_t)(HID * KSM + NB * HID + TSTEPS * NB + SLOTS * 8 + 64 + 640)
        * sizeof(float);   // 176,896 B

    cudaFuncSetAttribute(postnorm_rnn_kernel,
                         cudaFuncAttributeMaxDynamicSharedMemorySize,
                         (int)SMEM_BYTES);

    postnorm_rnn_kernel<<<BATCH / NB, NTH, SMEM_BYTES>>>(
        x, W_embed, b_embed, W_update, b_update, gamma, beta,
        W_out, b_out, cs, (float*)d_out);
}